// round 17
// baseline (speedup 1.0000x reference)
#include <cuda_runtime.h>

// RNN forward, fused persistent kernel. B=256, T=1024, IN=4, H=256, OUT=1.
// 128 CTAs x 256 threads; CTA = 2 batches.
// R17 = champion + batch-interleaved phases:
//   Phase A: b0 full FMA (reg+streamed weights) + b1's streamed-weight rows
//            (streamed weights still loaded ONCE, used 4x)  -> B1
//   tail0 (b0 reduce/tanh) || Phase B: b1 register-weight rows (independent
//            FFMA2 fills tail0's latency shadow)            -> B2
//   tail1 (b1 reduce/tanh)                                  -> B3
// hbuf single-buffered (audit: every write->read crossing has >=1 barrier).
// Wh: 88 u64-pairs/thread in regs + 20 ulonglong2/step streamed (unchanged).

typedef unsigned long long u64;

#define T_LEN   1024
#define KG_LEN  64

__device__ __forceinline__ u64 ffma2(u64 a, u64 b, u64 c) {
    u64 d;
    asm("fma.rn.f32x2 %0, %1, %2, %3;" : "=l"(d) : "l"(a), "l"(b), "l"(c));
    return d;
}
__device__ __forceinline__ float lo32(u64 v) { return __uint_as_float((unsigned)(v & 0xffffffffu)); }
__device__ __forceinline__ float hi32(u64 v) { return __uint_as_float((unsigned)(v >> 32)); }

__device__ __forceinline__ float fast_tanh(float x) {
    float a = fabsf(x);
    float e = __expf(2.0f * a);
    float r = 1.0f - __fdividef(2.0f, e + 1.0f);
    return copysignf(r, x);
}

// shared memory byte offsets
#define SM_WHS   0                  // ulonglong2 WHS[8][20][32]   = 81920 B
#define SM_HBUF  81920              // float hbuf[2][256]          = 2048 B (single-buffered)
#define SM_PB0   83968              // float pb0[4][256]           = 4096 B
#define SM_PB1   88064              // float pb1[4][256]           = 4096 B
#define SM_XS    92160              // float xs[2][8]              = 64 B
#define SM_TOTAL 92224

__global__ void __launch_bounds__(256, 1)
rnn_kernel(const float* __restrict__ x,        // [256][1024][4]
           const float* __restrict__ W_i2h,    // [256][260]  (cols 0..3 = Wx, 4..259 = Wh)
           const float* __restrict__ b_i2h,    // [256]
           const float* __restrict__ W_h2o,    // [256]
           const float* __restrict__ b_h2o,    // [1]
           const float* __restrict__ init_h,   // [256]
           float* __restrict__ out)            // [256]
{
    extern __shared__ unsigned char sm[];
    ulonglong2* WHS = (ulonglong2*)(sm + SM_WHS);
    float* hbuf = (float*)(sm + SM_HBUF);       // [b][256]
    float* pb0  = (float*)(sm + SM_PB0);        // [kg][256]
    float* pb1  = (float*)(sm + SM_PB1);        // [kg][256]
    float* xs   = (float*)(sm + SM_XS);

    const int t  = threadIdx.x;
    const int w  = t >> 5;
    const int l  = t & 31;
    const int kg = w & 3;             // k-group: k in [64*kg, 64*kg+64)
    const int hg = w >> 2;            // h-group: h in [128*hg, 128*hg+128)
    const int kbase = kg * KG_LEN;

    const int b0 = blockIdx.x * 2;
    const int h0r = hg * 128 + l;

    // permuted row assignment: row_i = h0r + 32*((i + kg) & 3); row_0 == t
    const int row1 = h0r + 32 * ((kg + 1) & 3);
    const int row2 = h0r + 32 * ((kg + 2) & 3);
    const int row3 = h0r + 32 * ((kg + 3) & 3);

    // ---- Wh: row0 (== t) and row1 fully + first 24 pairs of row2 in registers
    //      (88 pairs = 176 regs); rest of row2 + all of row3 in smem
    //      (20 ulonglong2 per thread = 80KB/CTA) ----
    u64 wreg[88];
    {
        const ulonglong2* rp0 = (const ulonglong2*)(W_i2h + (size_t)t * 260 + 4 + kbase);
        #pragma unroll
        for (int jj = 0; jj < 16; jj++) {
            ulonglong2 v = rp0[jj];
            wreg[2*jj]     = v.x;
            wreg[2*jj + 1] = v.y;
        }
        const ulonglong2* rp1 = (const ulonglong2*)(W_i2h + (size_t)row1 * 260 + 4 + kbase);
        #pragma unroll
        for (int jj = 0; jj < 16; jj++) {
            ulonglong2 v = rp1[jj];
            wreg[32 + 2*jj]     = v.x;
            wreg[32 + 2*jj + 1] = v.y;
        }
        const ulonglong2* rp2 = (const ulonglong2*)(W_i2h + (size_t)row2 * 260 + 4 + kbase);
        #pragma unroll
        for (int jj = 0; jj < 12; jj++) {
            ulonglong2 v = rp2[jj];
            wreg[64 + 2*jj]     = v.x;
            wreg[64 + 2*jj + 1] = v.y;
        }
        #pragma unroll
        for (int jj = 12; jj < 16; jj++)
            WHS[(w*20 + (jj - 12))*32 + l] = rp2[jj];
        const ulonglong2* rp3 = (const ulonglong2*)(W_i2h + (size_t)row3 * 260 + 4 + kbase);
        #pragma unroll
        for (int jj = 0; jj < 16; jj++)
            WHS[(w*20 + 4 + jj)*32 + l] = rp3[jj];
    }

    // reducer-role parameters for h = t
    const float4 wx = *(const float4*)(W_i2h + (size_t)t * 260);   // Wx[t][0..3]
    const float bi = b_i2h[t];
    const float wo = W_h2o[t];
    const float bo = b_h2o[0];

    // init hidden state and x for step 0
    {
        float hv = init_h[t];
        hbuf[0*256 + t] = hv;
        hbuf[1*256 + t] = hv;
        if (t < 2) {
            float4 xv = *(const float4*)(x + ((size_t)(b0 + t) * T_LEN + 0) * 4);
            *(float4*)(xs + t*4) = xv;
        }
    }
    __syncthreads();

    float pool0 = 0.0f, pool1 = 0.0f;
    int cur = 0;

    // tail load offsets for the 3 other k-groups (element index into pb0/pb1)
    const int o1 = ((kg + 1) & 3) * 256 + t;
    const int o2 = ((kg + 2) & 3) * 256 + t;
    const int o3 = ((kg + 3) & 3) * 256 + t;

    const ulonglong2* hp0 = (const ulonglong2*)(hbuf + 0*256 + kbase);
    const ulonglong2* hp1 = (const ulonglong2*)(hbuf + 1*256 + kbase);

    for (int step = 0; step < T_LEN; step++) {
        const int nxt = cur ^ 1;

        // ---- Phase A: b0 all rows (reg + streamed) + b1 streamed rows ----
        u64 a0 = 0ULL, a1 = 0ULL, a2 = 0ULL, a3 = 0ULL;   // b0 rows 0..3
        u64 c2 = 0ULL, c3 = 0ULL;                          // b1 row2(streamed part), row3

        #pragma unroll
        for (int jj = 0; jj < 16; jj++) {
            ulonglong2 h0v = hp0[jj];
            ulonglong2 h1v = hp1[jj];
            u64 wa = wreg[2*jj];
            u64 wb = wreg[2*jj + 1];
            a0 = ffma2(wa, h0v.x, a0);
            a0 = ffma2(wb, h0v.y, a0);
            wa = wreg[32 + 2*jj];
            wb = wreg[32 + 2*jj + 1];
            a1 = ffma2(wa, h0v.x, a1);
            a1 = ffma2(wb, h0v.y, a1);
            if (jj < 12) {
                u64 wa2 = wreg[64 + 2*jj];
                u64 wb2 = wreg[64 + 2*jj + 1];
                a2 = ffma2(wa2, h0v.x, a2);
                a2 = ffma2(wb2, h0v.y, a2);
            } else {
                ulonglong2 v = WHS[(w*20 + (jj - 12))*32 + l];
                a2 = ffma2(v.x, h0v.x, a2);
                a2 = ffma2(v.y, h0v.y, a2);
                c2 = ffma2(v.x, h1v.x, c2);      // b1 row2, streamed part
                c2 = ffma2(v.y, h1v.y, c2);
            }
            ulonglong2 v3 = WHS[(w*20 + 4 + jj)*32 + l];
            a3 = ffma2(v3.x, h0v.x, a3);
            a3 = ffma2(v3.y, h0v.y, a3);
            c3 = ffma2(v3.x, h1v.x, c3);         // b1 row3 (full, streamed)
            c3 = ffma2(v3.y, h1v.y, c3);
        }

        // own b0 partial (row0 == t) stays in registers
        float s00 = lo32(a0) + hi32(a0);
        // foreign b0 partials + completed b1 row3
        pb0[kg*256 + row1] = lo32(a1) + hi32(a1);
        pb0[kg*256 + row2] = lo32(a2) + hi32(a2);
        pb0[kg*256 + row3] = lo32(a3) + hi32(a3);
        pb1[kg*256 + row3] = lo32(c3) + hi32(c3);

        // stage x for next step (short live range)
        if (t < 2) {
            int tn = (step < T_LEN - 1) ? (step + 1) : step;
            float4 xv = *(const float4*)(x + ((size_t)(b0 + t) * T_LEN + tn) * 4);
            *(float4*)(xs + nxt*8 + t*4) = xv;
        }
        __syncthreads();                         // B1

        // ---- tail0 (b0 reduce/tanh) overlapped with Phase B (b1 reg rows) ----
        float r0 = s00 + ((pb0[o1] + pb0[o2]) + pb0[o3]);
        const float* xsc = xs + cur*8;
        float xp0 = bi + wx.x*xsc[0] + wx.y*xsc[1] + wx.z*xsc[2] + wx.w*xsc[3];
        float hn0 = fast_tanh(xp0 + r0);
        pool0 += hn0;
        hbuf[0*256 + t] = hn0;

        u64 d0 = 0ULL, d1 = 0ULL;                // b1 rows 0,1
        #pragma unroll
        for (int jj = 0; jj < 16; jj++) {
            ulonglong2 h1v = hp1[jj];
            u64 wa = wreg[2*jj];
            u64 wb = wreg[2*jj + 1];
            d0 = ffma2(wa, h1v.x, d0);
            d0 = ffma2(wb, h1v.y, d0);
            wa = wreg[32 + 2*jj];
            wb = wreg[32 + 2*jj + 1];
            d1 = ffma2(wa, h1v.x, d1);
            d1 = ffma2(wb, h1v.y, d1);
            if (jj < 12) {
                u64 wa2 = wreg[64 + 2*jj];
                u64 wb2 = wreg[64 + 2*jj + 1];
                c2 = ffma2(wa2, h1v.x, c2);      // finish b1 row2
                c2 = ffma2(wb2, h1v.y, c2);
            }
        }
        float s10 = lo32(d0) + hi32(d0);         // own b1 partial, stays in regs
        pb1[kg*256 + row1] = lo32(d1) + hi32(d1);
        pb1[kg*256 + row2] = lo32(c2) + hi32(c2);
        __syncthreads();                         // B2

        // ---- tail1 (b1 reduce/tanh) ----
        float r1 = s10 + ((pb1[o1] + pb1[o2]) + pb1[o3]);
        float xp1 = bi + wx.x*xsc[4] + wx.y*xsc[5] + wx.z*xsc[6] + wx.w*xsc[7];
        float hn1 = fast_tanh(xp1 + r1);
        pool1 += hn1;
        hbuf[1*256 + t] = hn1;
        __syncthreads();                         // B3
        cur = nxt;
    }

    // ---- output head: out[b] = mean_t(h)[b] . W_h2o + b_h2o ----
    float v0 = pool0 * (1.0f / 1024.0f) * wo;
    float v1 = pool1 * (1.0f / 1024.0f) * wo;
    #pragma unroll
    for (int o = 16; o > 0; o >>= 1) {
        v0 += __shfl_down_sync(0xffffffffu, v0, o);
        v1 += __shfl_down_sync(0xffffffffu, v1, o);
    }
    if (l == 0) { pb0[w] = v0; pb0[8 + w] = v1; }
    __syncthreads();
    if (t == 0) {
        float s = 0.0f;
        #pragma unroll
        for (int i = 0; i < 8; i++) s += pb0[i];
        out[b0] = s + bo;
    } else if (t == 1) {
        float s = 0.0f;
        #pragma unroll
        for (int i = 0; i < 8; i++) s += pb0[8 + i];
        out[b0 + 1] = s + bo;
    }
}

extern "C" void kernel_launch(void* const* d_in, const int* in_sizes, int n_in,
                              void* d_out, int out_size) {
    const float* x     = (const float*)d_in[0];
    const float* W_i2h = (const float*)d_in[1];
    const float* b_i2h = (const float*)d_in[2];
    const float* W_h2o = (const float*)d_in[3];
    const float* b_h2o = (const float*)d_in[4];
    const float* ih    = (const float*)d_in[5];
    float* outp = (float*)d_out;

    cudaFuncSetAttribute(rnn_kernel, cudaFuncAttributeMaxDynamicSharedMemorySize, SM_TOTAL);
    rnn_kernel<<<128, 256, SM_TOTAL>>>(x, W_i2h, b_i2h, W_h2o, b_h2o, ih, outp);
}